// round 14
// baseline (speedup 1.0000x reference)
#include <cuda_runtime.h>
#include <cuda_bf16.h>
#include <cstdint>

// ---------------- problem constants ----------------
#define NB   8
#define NC   2048
#define NF   8192
#define CDIM 256
#define CS   64
#define OUTD 256
#define MTOT (NB*NF)        // 65536
#define K1   (CDIM+CS)      // 320
#define HSIZE (MTOT*OUTD)
#define NKB1 20             // K1/16 k-blocks for GEMM1
#define NKB2 16             // 256/16 k-blocks for GEMM2
#define NNB  32             // 256/8 n-blocks
#define HALF 1024           // candidates per KNN phase-A block

// ---------------- scratch (static device globals) ----------------
__device__ int   g_idx[MTOT*3];
__device__ float g_w[MTOT*3];
__device__ float g_ps[2*MTOT*3];
__device__ int   g_pi[2*MTOT*3];
__device__ __align__(16) uint32_t g_hfrag_hi[(MTOT/16)*NKB2*128];
__device__ __align__(16) uint32_t g_hfrag_lo[(MTOT/16)*NKB2*128];
__device__ __align__(16) uint32_t g_w1f_hi[NNB*NKB1*64];
__device__ __align__(16) uint32_t g_w1f_lo[NNB*NKB1*64];
__device__ __align__(16) uint32_t g_w2f_hi[NNB*NKB2*64];
__device__ __align__(16) uint32_t g_w2f_lo[NNB*NKB2*64];

// ---------------- helpers ----------------
__device__ __forceinline__ uint32_t smem_u32(const void* p) {
    uint32_t a;
    asm("{ .reg .u64 t; cvta.to.shared.u64 t, %1; cvt.u32.u64 %0, t; }" : "=r"(a) : "l"(p));
    return a;
}

#define LDSM_X4(r0, r1, r2, r3, addr) \
    asm volatile("ldmatrix.sync.aligned.m8n8.x4.shared.b16 {%0,%1,%2,%3}, [%4];" \
        : "=r"(r0), "=r"(r1), "=r"(r2), "=r"(r3) : "r"(addr))

#define MMA_BF16(d, a, b0, b1) \
    asm volatile("mma.sync.aligned.m16n8k16.row.col.f32.bf16.bf16.f32 " \
        "{%0,%1,%2,%3}, {%4,%5,%6,%7}, {%8,%9}, {%0,%1,%2,%3};" \
        : "+f"((d)[0]), "+f"((d)[1]), "+f"((d)[2]), "+f"((d)[3]) \
        : "r"((a)[0]), "r"((a)[1]), "r"((a)[2]), "r"((a)[3]), "r"(b0), "r"(b1))

__device__ __forceinline__ void split2(float v0, float v1, uint32_t& hi, uint32_t& lo) {
    __nv_bfloat16 h0 = __float2bfloat16(v0);
    __nv_bfloat16 h1 = __float2bfloat16(v1);
    __nv_bfloat16 l0 = __float2bfloat16(v0 - __bfloat162float(h0));
    __nv_bfloat16 l1 = __float2bfloat16(v1 - __bfloat162float(h1));
    hi = ((uint32_t)__bfloat16_as_ushort(h1) << 16) | (uint32_t)__bfloat16_as_ushort(h0);
    lo = ((uint32_t)__bfloat16_as_ushort(l1) << 16) | (uint32_t)__bfloat16_as_ushort(l0);
}

__device__ __forceinline__ void ins3(float s, int j,
                                     float& s0, float& s1, float& s2,
                                     int& i0, int& i1, int& i2) {
    if (s > s2) {
        if (s > s1) {
            s2 = s1; i2 = i1;
            if (s > s0) { s1 = s0; i1 = i0; s0 = s; i0 = j; }
            else        { s1 = s;  i1 = j; }
        } else { s2 = s; i2 = j; }
    }
}

// ---------------- fused misc: knnA (0..511), prep (512..591), aux (592..1359) ----------------
__global__ void misc_kernel(const float* __restrict__ pos,
                            const float* __restrict__ pos_skip,
                            const int*  __restrict__ batch_skip,
                            const float* __restrict__ W1,
                            const float* __restrict__ W2,
                            float* __restrict__ out) {
    __shared__ float sx[HALF], sy[HALF], sz[HALF], sw[HALF];
    int blk = blockIdx.x;
    int tid = threadIdx.x;

    if (blk < 512) {
        int half = blk & 1;
        int grp = blk >> 1;
        int b = grp >> 5;
        int blk_in = grp & 31;
        int jbase = half * HALF;
        const float* cp = pos + ((size_t)b * NC + jbase) * 3;
        for (int i = tid; i < HALF; i += 256) {
            float cx = cp[i*3+0], cy = cp[i*3+1], cz = cp[i*3+2];
            sx[i] = cx; sy[i] = cy; sz[i] = cz;
            sw[i] = -0.5f * (cx*cx + cy*cy + cz*cz);
        }
        __syncthreads();

        int p = b * NF + blk_in * 256 + tid;
        float fx = pos_skip[p*3+0], fy = pos_skip[p*3+1], fz = pos_skip[p*3+2];

        float a0 = -1e30f, a1 = -1e30f, a2 = -1e30f;
        int   ai0 = 0,     ai1 = 0,     ai2 = 0;

        #pragma unroll 2
        for (int j = 0; j < HALF; j += 4) {
            float4 X = *(const float4*)&sx[j];
            float4 Y = *(const float4*)&sy[j];
            float4 Z = *(const float4*)&sz[j];
            float4 W = *(const float4*)&sw[j];
            float sa = fmaf(fz, Z.x, fmaf(fy, Y.x, fmaf(fx, X.x, W.x)));
            float sb = fmaf(fz, Z.y, fmaf(fy, Y.y, fmaf(fx, X.y, W.y)));
            float sc = fmaf(fz, Z.z, fmaf(fy, Y.z, fmaf(fx, X.z, W.z)));
            float sd = fmaf(fz, Z.w, fmaf(fy, Y.w, fmaf(fx, X.w, W.w)));
            float smax = fmaxf(fmaxf(sa, sb), fmaxf(sc, sd));
            if (smax > a2) {
                ins3(sa, j+0, a0, a1, a2, ai0, ai1, ai2);
                ins3(sb, j+1, a0, a1, a2, ai0, ai1, ai2);
                ins3(sc, j+2, a0, a1, a2, ai0, ai1, ai2);
                ins3(sd, j+3, a0, a1, a2, ai0, ai1, ai2);
            }
        }

        int base = (half * MTOT + p) * 3;
        g_ps[base+0] = a0; g_ps[base+1] = a1; g_ps[base+2] = a2;
        g_pi[base+0] = b*NC + jbase + ai0;
        g_pi[base+1] = b*NC + jbase + ai1;
        g_pi[base+2] = b*NC + jbase + ai2;
    } else if (blk < 512 + 80) {
        int t = (blk - 512) * 256 + tid;
        if (t < NNB * NKB1 * 32) {
            int lane = t & 31;
            int kb = (t >> 5) % NKB1;
            int nb = t / (32 * NKB1);
            int n = nb*8 + (lane >> 2);
            int k0 = kb*16 + (lane & 3)*2;
            float v0 = W1[(k0+0)*OUTD + n], v1 = W1[(k0+1)*OUTD + n];
            float v8 = W1[(k0+8)*OUTD + n], v9 = W1[(k0+9)*OUTD + n];
            uint32_t h0, l0, h1, l1;
            split2(v0, v1, h0, l0);
            split2(v8, v9, h1, l1);
            int idx = (nb*NKB1 + kb)*64 + lane*2;
            g_w1f_hi[idx] = h0; g_w1f_hi[idx+1] = h1;
            g_w1f_lo[idx] = l0; g_w1f_lo[idx+1] = l1;
        }
        if (t < NNB * NKB2 * 32) {
            int lane = t & 31;
            int kb = (t >> 5) & 15;
            int nb = t >> 9;
            int n = nb*8 + (lane >> 2);
            int k0 = kb*16 + (lane & 3)*2;
            float v0 = W2[(k0+0)*OUTD + n], v1 = W2[(k0+1)*OUTD + n];
            float v8 = W2[(k0+8)*OUTD + n], v9 = W2[(k0+9)*OUTD + n];
            uint32_t h0, l0, h1, l1;
            split2(v0, v1, h0, l0);
            split2(v8, v9, h1, l1);
            int idx = (nb*NKB2 + kb)*64 + lane*2;
            g_w2f_hi[idx] = h0; g_w2f_hi[idx+1] = h1;
            g_w2f_lo[idx] = l0; g_w2f_lo[idx+1] = l1;
        }
    } else {
        int i = (blk - 592) * 256 + tid;
        if (i < MTOT*3) out[HSIZE + i] = pos_skip[i];
        if (i < MTOT)   out[HSIZE + MTOT*3 + i] = (float)batch_skip[i];
    }
}

// ---------------- KNN phase B: merge halves, exact distances, weights ----------------
__global__ void knn_merge_kernel(const float* __restrict__ pos,
                                 const float* __restrict__ pos_skip) {
    int p = blockIdx.x * 256 + threadIdx.x;
    int b0 = p * 3;
    int b1 = (MTOT + p) * 3;

    float s0 = g_ps[b0+0], s1 = g_ps[b0+1], s2 = g_ps[b0+2];
    int   i0 = g_pi[b0+0], i1 = g_pi[b0+1], i2 = g_pi[b0+2];
    ins3(g_ps[b1+0], g_pi[b1+0], s0, s1, s2, i0, i1, i2);
    ins3(g_ps[b1+1], g_pi[b1+1], s0, s1, s2, i0, i1, i2);
    ins3(g_ps[b1+2], g_pi[b1+2], s0, s1, s2, i0, i1, i2);

    float fx = pos_skip[p*3+0], fy = pos_skip[p*3+1], fz = pos_skip[p*3+2];
    float dx, dy, dz;
    dx = fx - pos[i0*3+0]; dy = fy - pos[i0*3+1]; dz = fz - pos[i0*3+2];
    float d0 = dx*dx + dy*dy + dz*dz;
    dx = fx - pos[i1*3+0]; dy = fy - pos[i1*3+1]; dz = fz - pos[i1*3+2];
    float d1 = dx*dx + dy*dy + dz*dz;
    dx = fx - pos[i2*3+0]; dy = fy - pos[i2*3+1]; dz = fz - pos[i2*3+2];
    float d2 = dx*dx + dy*dy + dz*dz;
    float w0 = 1.0f / fmaxf(d0, 1e-16f);
    float w1 = 1.0f / fmaxf(d1, 1e-16f);
    float w2 = 1.0f / fmaxf(d2, 1e-16f);
    float inv = 1.0f / (w0 + w1 + w2);
    g_idx[p*3+0] = i0;
    g_idx[p*3+1] = i1;
    g_idx[p*3+2] = i2;
    g_w[p*3+0] = w0 * inv;
    g_w[p*3+1] = w1 * inv;
    g_w[p*3+2] = w2 * inv;
}

// ---------------- GEMM1: pipelined gather+interp + Linear1 + ReLU -> h fragments ----------------
#define RS 40   // smem row stride (bf16)

__global__ __launch_bounds__(256, 2)
void gemm1_kernel(const float* __restrict__ x,
                  const float* __restrict__ x_skip,
                  const float* __restrict__ b1) {
    __shared__ __nv_bfloat16 As_hi[2][64*RS], As_lo[2][64*RS];

    int tid = threadIdx.x;
    int wid = tid >> 5;
    int lane = tid & 31;
    int warp_m = wid & 1;
    int warp_n = wid >> 1;
    int bm = blockIdx.x * 64;

    int lrow = tid >> 2;
    int koff = (tid & 3) * 8;
    int r = bm + lrow;
    int i0 = g_idx[r*3+0] * CDIM, i1 = g_idx[r*3+1] * CDIM, i2 = g_idx[r*3+2] * CDIM;
    float w0 = g_w[r*3+0], w1 = g_w[r*3+1], w2 = g_w[r*3+2];
    int sbase = lrow * RS + koff;

    uint32_t aOff = (uint32_t)(((warp_m*32 + (lane & 15)) * RS + (lane >> 4) * 8) * 2);
    uint32_t sH[2] = { smem_u32(As_hi[0]) + aOff, smem_u32(As_hi[1]) + aOff };
    uint32_t sL[2] = { smem_u32(As_lo[0]) + aOff, smem_u32(As_lo[1]) + aOff };

    float acc[2][8][4];
    #pragma unroll
    for (int i = 0; i < 2; i++)
        #pragma unroll
        for (int j = 0; j < 8; j++)
            #pragma unroll
            for (int q = 0; q < 4; q++) acc[i][j][q] = 0.0f;

    // ---- prologue: build chunk 0 into buf 0 ----
    {
        float4 a0 = *(const float4*)(x + i0 + koff);
        float4 a1 = *(const float4*)(x + i0 + koff + 4);
        float4 b0 = *(const float4*)(x + i1 + koff);
        float4 b1v = *(const float4*)(x + i1 + koff + 4);
        float4 c0 = *(const float4*)(x + i2 + koff);
        float4 c1 = *(const float4*)(x + i2 + koff + 4);
        uint32_t hp[4], lp[4];
        split2(w0*a0.x + w1*b0.x + w2*c0.x,  w0*a0.y + w1*b0.y + w2*c0.y,  hp[0], lp[0]);
        split2(w0*a0.z + w1*b0.z + w2*c0.z,  w0*a0.w + w1*b0.w + w2*c0.w,  hp[1], lp[1]);
        split2(w0*a1.x + w1*b1v.x + w2*c1.x, w0*a1.y + w1*b1v.y + w2*c1.y, hp[2], lp[2]);
        split2(w0*a1.z + w1*b1v.z + w2*c1.z, w0*a1.w + w1*b1v.w + w2*c1.w, hp[3], lp[3]);
        *(uint4*)(As_hi[0] + sbase) = make_uint4(hp[0], hp[1], hp[2], hp[3]);
        *(uint4*)(As_lo[0] + sbase) = make_uint4(lp[0], lp[1], lp[2], lp[3]);
    }
    __syncthreads();

    for (int c = 0; c < 10; c++) {
        int buf = c & 1;
        float4 ga0, ga1, gb0, gb1, gc0, gc1;
        bool have_next = (c + 1 < 10);
        bool next_is_x = ((c + 1) * 32 < CDIM);
        if (have_next) {
            if (next_is_x) {
                int k = (c + 1) * 32 + koff;
                ga0 = *(const float4*)(x + i0 + k);
                ga1 = *(const float4*)(x + i0 + k + 4);
                gb0 = *(const float4*)(x + i1 + k);
                gb1 = *(const float4*)(x + i1 + k + 4);
                gc0 = *(const float4*)(x + i2 + k);
                gc1 = *(const float4*)(x + i2 + k + 4);
            } else {
                int ks = (c + 1) * 32 - CDIM + koff;
                ga0 = *(const float4*)(x_skip + (size_t)r * CS + ks);
                ga1 = *(const float4*)(x_skip + (size_t)r * CS + ks + 4);
            }
        }

        #pragma unroll
        for (int ks = 0; ks < 2; ks++) {
            int kb = c*2 + ks;
            uint32_t ko = ks * 32;
            uint32_t ah[2][4], al[2][4];
            #pragma unroll
            for (int mt = 0; mt < 2; mt++) {
                LDSM_X4(ah[mt][0], ah[mt][1], ah[mt][2], ah[mt][3], sH[buf] + mt*16*RS*2 + ko);
                LDSM_X4(al[mt][0], al[mt][1], al[mt][2], al[mt][3], sL[buf] + mt*16*RS*2 + ko);
            }
            // software-pipelined B-frag loads
            uint2 bh = *(const uint2*)&g_w1f_hi[((warp_n*8)*NKB1 + kb)*64 + lane*2];
            uint2 bl = *(const uint2*)&g_w1f_lo[((warp_n*8)*NKB1 + kb)*64 + lane*2];
            #pragma unroll
            for (int nb = 0; nb < 8; nb++) {
                uint2 bhn, bln;
                if (nb < 7) {
                    int nblock = warp_n*8 + nb + 1;
                    bhn = *(const uint2*)&g_w1f_hi[(nblock*NKB1 + kb)*64 + lane*2];
                    bln = *(const uint2*)&g_w1f_lo[(nblock*NKB1 + kb)*64 + lane*2];
                }
                #pragma unroll
                for (int mt = 0; mt < 2; mt++) {
                    float* d = acc[mt][nb];
                    MMA_BF16(d, ah[mt], bh.x, bh.y);
                    MMA_BF16(d, ah[mt], bl.x, bl.y);
                    MMA_BF16(d, al[mt], bh.x, bh.y);
                }
                bh = bhn; bl = bln;
            }
        }

        if (have_next) {
            float v[8];
            if (next_is_x) {
                v[0] = w0*ga0.x + w1*gb0.x + w2*gc0.x;
                v[1] = w0*ga0.y + w1*gb0.y + w2*gc0.y;
                v[2] = w0*ga0.z + w1*gb0.z + w2*gc0.z;
                v[3] = w0*ga0.w + w1*gb0.w + w2*gc0.w;
                v[4] = w0*ga1.x + w1*gb1.x + w2*gc1.x;
                v[5] = w0*ga1.y + w1*gb1.y + w2*gc1.y;
                v[6] = w0*ga1.z + w1*gb1.z + w2*gc1.z;
                v[7] = w0*ga1.w + w1*gb1.w + w2*gc1.w;
            } else {
                v[0] = ga0.x; v[1] = ga0.y; v[2] = ga0.z; v[3] = ga0.w;
                v[4] = ga1.x; v[5] = ga1.y; v[6] = ga1.z; v[7] = ga1.w;
            }
            uint32_t hp[4], lp[4];
            split2(v[0], v[1], hp[0], lp[0]);
            split2(v[2], v[3], hp[1], lp[1]);
            split2(v[4], v[5], hp[2], lp[2]);
            split2(v[6], v[7], hp[3], lp[3]);
            *(uint4*)(As_hi[buf^1] + sbase) = make_uint4(hp[0], hp[1], hp[2], hp[3]);
            *(uint4*)(As_lo[buf^1] + sbase) = make_uint4(lp[0], lp[1], lp[2], lp[3]);
        }
        __syncthreads();
    }

    // ---- epilogue: bias + ReLU -> h A-fragments ----
    #pragma unroll
    for (int mt = 0; mt < 2; mt++) {
        int mblock = blockIdx.x*4 + warp_m*2 + mt;
        #pragma unroll
        for (int fp = 0; fp < 4; fp++) {
            int f0 = 2*fp, f1 = 2*fp + 1;
            int kbh = warp_n*4 + fp;
            int col0 = (warp_n*8 + f0)*8 + (lane & 3)*2;
            float2 bb0 = *(const float2*)(b1 + col0);
            float2 bb1 = *(const float2*)(b1 + col0 + 8);
            float v0 = fmaxf(acc[mt][f0][0] + bb0.x, 0.0f);
            float v1 = fmaxf(acc[mt][f0][1] + bb0.y, 0.0f);
            float v2 = fmaxf(acc[mt][f0][2] + bb0.x, 0.0f);
            float v3 = fmaxf(acc[mt][f0][3] + bb0.y, 0.0f);
            float v4 = fmaxf(acc[mt][f1][0] + bb1.x, 0.0f);
            float v5 = fmaxf(acc[mt][f1][1] + bb1.y, 0.0f);
            float v6 = fmaxf(acc[mt][f1][2] + bb1.x, 0.0f);
            float v7 = fmaxf(acc[mt][f1][3] + bb1.y, 0.0f);
            uint32_t a0h, a0l, a1h, a1l, a2h, a2l, a3h, a3l;
            split2(v0, v1, a0h, a0l);
            split2(v2, v3, a1h, a1l);
            split2(v4, v5, a2h, a2l);
            split2(v6, v7, a3h, a3l);
            int fidx = (mblock*NKB2 + kbh)*32 + lane;
            ((uint4*)g_hfrag_hi)[fidx] = make_uint4(a0h, a1h, a2h, a3h);
            ((uint4*)g_hfrag_lo)[fidx] = make_uint4(a0l, a1l, a2l, a3l);
        }
    }
}

// ---------------- GEMM2: Linear2 + ReLU, W2 frags staged in SMEM ----------------
// CTA: 8 warps, same n-quarter, 8 m-strips (256 rows). grid = 256 mgroups x 4 nq.
__global__ __launch_bounds__(256, 2)
void gemm2_kernel(const float* __restrict__ b2, float* __restrict__ out) {
    __shared__ __align__(16) uint32_t sWh[8192], sWl[8192];   // 64 KB

    int tid = threadIdx.x;
    int wid = tid >> 5;
    int lane = tid & 31;
    int mgroup = blockIdx.x >> 2;
    int nq = blockIdx.x & 3;

    // bulk-load this quarter's W2 fragments (contiguous 32 KB hi + 32 KB lo)
    {
        const uint4* srcH = (const uint4*)(g_w2f_hi + nq * 8192);
        const uint4* srcL = (const uint4*)(g_w2f_lo + nq * 8192);
        uint4* dstH = (uint4*)sWh;
        uint4* dstL = (uint4*)sWl;
        #pragma unroll
        for (int i = 0; i < 8; i++) {
            dstH[tid + i*256] = srcH[tid + i*256];
            dstL[tid + i*256] = srcL[tid + i*256];
        }
    }
    __syncthreads();

    int mstrip = mgroup * 8 + wid;
    const uint4* HF = (const uint4*)g_hfrag_hi;
    const uint4* LF = (const uint4*)g_hfrag_lo;
    int mb0 = mstrip * 2;

    float acc[2][8][4];
    #pragma unroll
    for (int i = 0; i < 2; i++)
        #pragma unroll
        for (int j = 0; j < 8; j++)
            #pragma unroll
            for (int q = 0; q < 4; q++) acc[i][j][q] = 0.0f;

    uint4 th[2], tl[2];
    #pragma unroll
    for (int mt = 0; mt < 2; mt++) {
        th[mt] = HF[((mb0 + mt)*NKB2 + 0)*32 + lane];
        tl[mt] = LF[((mb0 + mt)*NKB2 + 0)*32 + lane];
    }

    for (int kb = 0; kb < NKB2; kb++) {
        uint32_t ah[2][4], al[2][4];
        #pragma unroll
        for (int mt = 0; mt < 2; mt++) {
            ah[mt][0] = th[mt].x; ah[mt][1] = th[mt].y; ah[mt][2] = th[mt].z; ah[mt][3] = th[mt].w;
            al[mt][0] = tl[mt].x; al[mt][1] = tl[mt].y; al[mt][2] = tl[mt].z; al[mt][3] = tl[mt].w;
        }
        if (kb + 1 < NKB2) {
            #pragma unroll
            for (int mt = 0; mt < 2; mt++) {
                th[mt] = HF[((mb0 + mt)*NKB2 + kb + 1)*32 + lane];
                tl[mt] = LF[((mb0 + mt)*NKB2 + kb + 1)*32 + lane];
            }
        }
        #pragma unroll
        for (int nb = 0; nb < 8; nb++) {
            int so = (nb*NKB2 + kb)*64 + lane*2;
            uint2 bh = *(const uint2*)&sWh[so];
            uint2 bl = *(const uint2*)&sWl[so];
            #pragma unroll
            for (int mt = 0; mt < 2; mt++) {
                float* d = acc[mt][nb];
                MMA_BF16(d, ah[mt], bh.x, bh.y);
                MMA_BF16(d, ah[mt], bl.x, bl.y);
                MMA_BF16(d, al[mt], bh.x, bh.y);
            }
        }
    }

    #pragma unroll
    for (int mt = 0; mt < 2; mt++) {
        int r0 = mstrip*32 + mt*16 + (lane >> 2);
        #pragma unroll
        for (int nb = 0; nb < 8; nb++) {
            int col = (nq*8 + nb)*8 + (lane & 3)*2;
            float2 bb = *(const float2*)(b2 + col);
            float2 o0, o1;
            o0.x = fmaxf(acc[mt][nb][0] + bb.x, 0.0f);
            o0.y = fmaxf(acc[mt][nb][1] + bb.y, 0.0f);
            o1.x = fmaxf(acc[mt][nb][2] + bb.x, 0.0f);
            o1.y = fmaxf(acc[mt][nb][3] + bb.y, 0.0f);
            *(float2*)(out + (size_t)r0 * OUTD + col) = o0;
            *(float2*)(out + (size_t)(r0+8) * OUTD + col) = o1;
        }
    }
}

// ---------------- launch ----------------
extern "C" void kernel_launch(void* const* d_in, const int* in_sizes, int n_in,
                              void* d_out, int out_size) {
    const float* x          = (const float*)d_in[0];
    const float* pos        = (const float*)d_in[1];
    const float* x_skip     = (const float*)d_in[3];
    const float* pos_skip   = (const float*)d_in[4];
    const int*   batch_skip = (const int*)d_in[5];
    const float* W1         = (const float*)d_in[6];
    const float* b1         = (const float*)d_in[7];
    const float* W2         = (const float*)d_in[8];
    const float* b2         = (const float*)d_in[9];
    float* out = (float*)d_out;

    misc_kernel<<<512 + 80 + 768, 256>>>(pos, pos_skip, batch_skip, W1, W2, out);
    knn_merge_kernel<<<MTOT/256, 256>>>(pos, pos_skip);
    gemm1_kernel<<<MTOT/64, 256>>>(x, x_skip, b1);
    gemm2_kernel<<<1024, 256>>>(b2, out);
}

// round 15
// speedup vs baseline: 1.0859x; 1.0859x over previous
#include <cuda_runtime.h>
#include <cuda_fp16.h>
#include <cstdint>

// ---------------- problem constants ----------------
#define NB   8
#define NC   2048
#define NF   8192
#define CDIM 256
#define CS   64
#define OUTD 256
#define MTOT (NB*NF)        // 65536
#define K1   (CDIM+CS)      // 320
#define HSIZE (MTOT*OUTD)
#define NKB1 20             // K1/16 k-blocks for GEMM1
#define NKB2 16             // 256/16 k-blocks for GEMM2
#define NNB  32             // 256/8 n-blocks
#define HALF 1024           // candidates per KNN phase-A block

// ---------------- scratch (static device globals) ----------------
__device__ int   g_idx[MTOT*3];
__device__ float g_w[MTOT*3];
__device__ float g_ps[2*MTOT*3];
__device__ int   g_pi[2*MTOT*3];
// h stored as mma A-fragments (fp16 hi/lo): [mblock][kblock][lane][4] u32
__device__ __align__(16) uint32_t g_hfrag_hi[(MTOT/16)*NKB2*128];
__device__ __align__(16) uint32_t g_hfrag_lo[(MTOT/16)*NKB2*128];
// weights as single-fp16 mma B-fragments: [nblock][kblock][lane][2] u32
__device__ __align__(16) uint32_t g_w1f[NNB*NKB1*64];
__device__ __align__(16) uint32_t g_w2f[NNB*NKB2*64];

// ---------------- helpers ----------------
__device__ __forceinline__ uint32_t smem_u32(const void* p) {
    uint32_t a;
    asm("{ .reg .u64 t; cvta.to.shared.u64 t, %1; cvt.u32.u64 %0, t; }" : "=r"(a) : "l"(p));
    return a;
}

#define LDSM_X4(r0, r1, r2, r3, addr) \
    asm volatile("ldmatrix.sync.aligned.m8n8.x4.shared.b16 {%0,%1,%2,%3}, [%4];" \
        : "=r"(r0), "=r"(r1), "=r"(r2), "=r"(r3) : "r"(addr))

#define MMA_F16(d, a, b0, b1) \
    asm volatile("mma.sync.aligned.m16n8k16.row.col.f32.f16.f16.f32 " \
        "{%0,%1,%2,%3}, {%4,%5,%6,%7}, {%8,%9}, {%0,%1,%2,%3};" \
        : "+f"((d)[0]), "+f"((d)[1]), "+f"((d)[2]), "+f"((d)[3]) \
        : "r"((a)[0]), "r"((a)[1]), "r"((a)[2]), "r"((a)[3]), "r"(b0), "r"(b1))

__device__ __forceinline__ uint32_t packh(__half a, __half b) {
    return ((uint32_t)__half_as_ushort(b) << 16) | (uint32_t)__half_as_ushort(a);
}

// fp16 hi/lo split of two fp32 values
__device__ __forceinline__ void split2h(float v0, float v1, uint32_t& hi, uint32_t& lo) {
    __half h0 = __float2half_rn(v0);
    __half h1 = __float2half_rn(v1);
    __half l0 = __float2half_rn(v0 - __half2float(h0));
    __half l1 = __float2half_rn(v1 - __half2float(h1));
    hi = packh(h0, h1);
    lo = packh(l0, l1);
}

__device__ __forceinline__ void ins3(float s, int j,
                                     float& s0, float& s1, float& s2,
                                     int& i0, int& i1, int& i2) {
    if (s > s2) {
        if (s > s1) {
            s2 = s1; i2 = i1;
            if (s > s0) { s1 = s0; i1 = i0; s0 = s; i0 = j; }
            else        { s1 = s;  i1 = j; }
        } else { s2 = s; i2 = j; }
    }
}

// ---------------- fused misc: knnA (0..511), prep (512..591), aux (592..1359) ----------------
__global__ void misc_kernel(const float* __restrict__ pos,
                            const float* __restrict__ pos_skip,
                            const int*  __restrict__ batch_skip,
                            const float* __restrict__ W1,
                            const float* __restrict__ W2,
                            float* __restrict__ out) {
    __shared__ float sx[HALF], sy[HALF], sz[HALF], sw[HALF];
    int blk = blockIdx.x;
    int tid = threadIdx.x;

    if (blk < 512) {
        int half = blk & 1;
        int grp = blk >> 1;
        int b = grp >> 5;
        int blk_in = grp & 31;
        int jbase = half * HALF;
        const float* cp = pos + ((size_t)b * NC + jbase) * 3;
        for (int i = tid; i < HALF; i += 256) {
            float cx = cp[i*3+0], cy = cp[i*3+1], cz = cp[i*3+2];
            sx[i] = cx; sy[i] = cy; sz[i] = cz;
            sw[i] = -0.5f * (cx*cx + cy*cy + cz*cz);
        }
        __syncthreads();

        int p = b * NF + blk_in * 256 + tid;
        float fx = pos_skip[p*3+0], fy = pos_skip[p*3+1], fz = pos_skip[p*3+2];

        float a0 = -1e30f, a1 = -1e30f, a2 = -1e30f;
        int   ai0 = 0,     ai1 = 0,     ai2 = 0;

        #pragma unroll 2
        for (int j = 0; j < HALF; j += 4) {
            float4 X = *(const float4*)&sx[j];
            float4 Y = *(const float4*)&sy[j];
            float4 Z = *(const float4*)&sz[j];
            float4 W = *(const float4*)&sw[j];
            float sa = fmaf(fz, Z.x, fmaf(fy, Y.x, fmaf(fx, X.x, W.x)));
            float sb = fmaf(fz, Z.y, fmaf(fy, Y.y, fmaf(fx, X.y, W.y)));
            float sc = fmaf(fz, Z.z, fmaf(fy, Y.z, fmaf(fx, X.z, W.z)));
            float sd = fmaf(fz, Z.w, fmaf(fy, Y.w, fmaf(fx, X.w, W.w)));
            float smax = fmaxf(fmaxf(sa, sb), fmaxf(sc, sd));
            if (smax > a2) {
                ins3(sa, j+0, a0, a1, a2, ai0, ai1, ai2);
                ins3(sb, j+1, a0, a1, a2, ai0, ai1, ai2);
                ins3(sc, j+2, a0, a1, a2, ai0, ai1, ai2);
                ins3(sd, j+3, a0, a1, a2, ai0, ai1, ai2);
            }
        }

        int base = (half * MTOT + p) * 3;
        g_ps[base+0] = a0; g_ps[base+1] = a1; g_ps[base+2] = a2;
        g_pi[base+0] = b*NC + jbase + ai0;
        g_pi[base+1] = b*NC + jbase + ai1;
        g_pi[base+2] = b*NC + jbase + ai2;
    } else if (blk < 512 + 80) {
        // ---- weight prep: W^T -> single-fp16 B-fragments ----
        int t = (blk - 512) * 256 + tid;
        if (t < NNB * NKB1 * 32) {
            int lane = t & 31;
            int kb = (t >> 5) % NKB1;
            int nb = t / (32 * NKB1);
            int n = nb*8 + (lane >> 2);
            int k0 = kb*16 + (lane & 3)*2;
            float v0 = W1[(k0+0)*OUTD + n], v1 = W1[(k0+1)*OUTD + n];
            float v8 = W1[(k0+8)*OUTD + n], v9 = W1[(k0+9)*OUTD + n];
            int idx = (nb*NKB1 + kb)*64 + lane*2;
            g_w1f[idx]   = packh(__float2half_rn(v0), __float2half_rn(v1));
            g_w1f[idx+1] = packh(__float2half_rn(v8), __float2half_rn(v9));
        }
        if (t < NNB * NKB2 * 32) {
            int lane = t & 31;
            int kb = (t >> 5) & 15;
            int nb = t >> 9;
            int n = nb*8 + (lane >> 2);
            int k0 = kb*16 + (lane & 3)*2;
            float v0 = W2[(k0+0)*OUTD + n], v1 = W2[(k0+1)*OUTD + n];
            float v8 = W2[(k0+8)*OUTD + n], v9 = W2[(k0+9)*OUTD + n];
            int idx = (nb*NKB2 + kb)*64 + lane*2;
            g_w2f[idx]   = packh(__float2half_rn(v0), __float2half_rn(v1));
            g_w2f[idx+1] = packh(__float2half_rn(v8), __float2half_rn(v9));
        }
    } else {
        int i = (blk - 592) * 256 + tid;
        if (i < MTOT*3) out[HSIZE + i] = pos_skip[i];
        if (i < MTOT)   out[HSIZE + MTOT*3 + i] = (float)batch_skip[i];
    }
}

// ---------------- KNN phase B: merge halves, exact distances, weights ----------------
__global__ void knn_merge_kernel(const float* __restrict__ pos,
                                 const float* __restrict__ pos_skip) {
    int p = blockIdx.x * 256 + threadIdx.x;
    int b0 = p * 3;
    int b1 = (MTOT + p) * 3;

    float s0 = g_ps[b0+0], s1 = g_ps[b0+1], s2 = g_ps[b0+2];
    int   i0 = g_pi[b0+0], i1 = g_pi[b0+1], i2 = g_pi[b0+2];
    ins3(g_ps[b1+0], g_pi[b1+0], s0, s1, s2, i0, i1, i2);
    ins3(g_ps[b1+1], g_pi[b1+1], s0, s1, s2, i0, i1, i2);
    ins3(g_ps[b1+2], g_pi[b1+2], s0, s1, s2, i0, i1, i2);

    float fx = pos_skip[p*3+0], fy = pos_skip[p*3+1], fz = pos_skip[p*3+2];
    float dx, dy, dz;
    dx = fx - pos[i0*3+0]; dy = fy - pos[i0*3+1]; dz = fz - pos[i0*3+2];
    float d0 = dx*dx + dy*dy + dz*dz;
    dx = fx - pos[i1*3+0]; dy = fy - pos[i1*3+1]; dz = fz - pos[i1*3+2];
    float d1 = dx*dx + dy*dy + dz*dz;
    dx = fx - pos[i2*3+0]; dy = fy - pos[i2*3+1]; dz = fz - pos[i2*3+2];
    float d2 = dx*dx + dy*dy + dz*dz;
    float w0 = 1.0f / fmaxf(d0, 1e-16f);
    float w1 = 1.0f / fmaxf(d1, 1e-16f);
    float w2 = 1.0f / fmaxf(d2, 1e-16f);
    float inv = 1.0f / (w0 + w1 + w2);
    g_idx[p*3+0] = i0;
    g_idx[p*3+1] = i1;
    g_idx[p*3+2] = i2;
    g_w[p*3+0] = w0 * inv;
    g_w[p*3+1] = w1 * inv;
    g_w[p*3+2] = w2 * inv;
}

// ---------------- GEMM1: pipelined gather+interp + Linear1 + ReLU -> h fragments ----------------
#define RS 40   // smem row stride (fp16)

__global__ __launch_bounds__(256, 2)
void gemm1_kernel(const float* __restrict__ x,
                  const float* __restrict__ x_skip,
                  const float* __restrict__ b1) {
    __shared__ __half As_hi[2][64*RS], As_lo[2][64*RS];

    int tid = threadIdx.x;
    int wid = tid >> 5;
    int lane = tid & 31;
    int warp_m = wid & 1;
    int warp_n = wid >> 1;
    int bm = blockIdx.x * 64;

    int lrow = tid >> 2;
    int koff = (tid & 3) * 8;
    int r = bm + lrow;
    int i0 = g_idx[r*3+0] * CDIM, i1 = g_idx[r*3+1] * CDIM, i2 = g_idx[r*3+2] * CDIM;
    float w0 = g_w[r*3+0], w1 = g_w[r*3+1], w2 = g_w[r*3+2];
    int sbase = lrow * RS + koff;

    uint32_t aOff = (uint32_t)(((warp_m*32 + (lane & 15)) * RS + (lane >> 4) * 8) * 2);
    uint32_t sH[2] = { smem_u32(As_hi[0]) + aOff, smem_u32(As_hi[1]) + aOff };
    uint32_t sL[2] = { smem_u32(As_lo[0]) + aOff, smem_u32(As_lo[1]) + aOff };

    float acc[2][8][4];
    #pragma unroll
    for (int i = 0; i < 2; i++)
        #pragma unroll
        for (int j = 0; j < 8; j++)
            #pragma unroll
            for (int q = 0; q < 4; q++) acc[i][j][q] = 0.0f;

    // ---- prologue: build chunk 0 into buf 0 ----
    {
        float4 a0 = *(const float4*)(x + i0 + koff);
        float4 a1 = *(const float4*)(x + i0 + koff + 4);
        float4 b0 = *(const float4*)(x + i1 + koff);
        float4 b1v = *(const float4*)(x + i1 + koff + 4);
        float4 c0 = *(const float4*)(x + i2 + koff);
        float4 c1 = *(const float4*)(x + i2 + koff + 4);
        uint32_t hp[4], lp[4];
        split2h(w0*a0.x + w1*b0.x + w2*c0.x,  w0*a0.y + w1*b0.y + w2*c0.y,  hp[0], lp[0]);
        split2h(w0*a0.z + w1*b0.z + w2*c0.z,  w0*a0.w + w1*b0.w + w2*c0.w,  hp[1], lp[1]);
        split2h(w0*a1.x + w1*b1v.x + w2*c1.x, w0*a1.y + w1*b1v.y + w2*c1.y, hp[2], lp[2]);
        split2h(w0*a1.z + w1*b1v.z + w2*c1.z, w0*a1.w + w1*b1v.w + w2*c1.w, hp[3], lp[3]);
        *(uint4*)(As_hi[0] + sbase) = make_uint4(hp[0], hp[1], hp[2], hp[3]);
        *(uint4*)(As_lo[0] + sbase) = make_uint4(lp[0], lp[1], lp[2], lp[3]);
    }
    __syncthreads();

    for (int c = 0; c < 10; c++) {
        int buf = c & 1;
        float4 ga0, ga1, gb0, gb1, gc0, gc1;
        bool have_next = (c + 1 < 10);
        bool next_is_x = ((c + 1) * 32 < CDIM);
        if (have_next) {
            if (next_is_x) {
                int k = (c + 1) * 32 + koff;
                ga0 = *(const float4*)(x + i0 + k);
                ga1 = *(const float4*)(x + i0 + k + 4);
                gb0 = *(const float4*)(x + i1 + k);
                gb1 = *(const float4*)(x + i1 + k + 4);
                gc0 = *(const float4*)(x + i2 + k);
                gc1 = *(const float4*)(x + i2 + k + 4);
            } else {
                int ks = (c + 1) * 32 - CDIM + koff;
                ga0 = *(const float4*)(x_skip + (size_t)r * CS + ks);
                ga1 = *(const float4*)(x_skip + (size_t)r * CS + ks + 4);
            }
        }

        #pragma unroll
        for (int ks = 0; ks < 2; ks++) {
            int kb = c*2 + ks;
            uint32_t ko = ks * 32;
            uint32_t ah[2][4], al[2][4];
            #pragma unroll
            for (int mt = 0; mt < 2; mt++) {
                LDSM_X4(ah[mt][0], ah[mt][1], ah[mt][2], ah[mt][3], sH[buf] + mt*16*RS*2 + ko);
                LDSM_X4(al[mt][0], al[mt][1], al[mt][2], al[mt][3], sL[buf] + mt*16*RS*2 + ko);
            }
            uint2 bb = *(const uint2*)&g_w1f[((warp_n*8)*NKB1 + kb)*64 + lane*2];
            #pragma unroll
            for (int nb = 0; nb < 8; nb++) {
                uint2 bbn;
                if (nb < 7) {
                    int nblock = warp_n*8 + nb + 1;
                    bbn = *(const uint2*)&g_w1f[(nblock*NKB1 + kb)*64 + lane*2];
                }
                #pragma unroll
                for (int mt = 0; mt < 2; mt++) {
                    float* d = acc[mt][nb];
                    MMA_F16(d, ah[mt], bb.x, bb.y);
                    MMA_F16(d, al[mt], bb.x, bb.y);
                }
                bb = bbn;
            }
        }

        if (have_next) {
            float v[8];
            if (next_is_x) {
                v[0] = w0*ga0.x + w1*gb0.x + w2*gc0.x;
                v[1] = w0*ga0.y + w1*gb0.y + w2*gc0.y;
                v[2] = w0*ga0.z + w1*gb0.z + w2*gc0.z;
                v[3] = w0*ga0.w + w1*gb0.w + w2*gc0.w;
                v[4] = w0*ga1.x + w1*gb1.x + w2*gc1.x;
                v[5] = w0*ga1.y + w1*gb1.y + w2*gc1.y;
                v[6] = w0*ga1.z + w1*gb1.z + w2*gc1.z;
                v[7] = w0*ga1.w + w1*gb1.w + w2*gc1.w;
            } else {
                v[0] = ga0.x; v[1] = ga0.y; v[2] = ga0.z; v[3] = ga0.w;
                v[4] = ga1.x; v[5] = ga1.y; v[6] = ga1.z; v[7] = ga1.w;
            }
            uint32_t hp[4], lp[4];
            split2h(v[0], v[1], hp[0], lp[0]);
            split2h(v[2], v[3], hp[1], lp[1]);
            split2h(v[4], v[5], hp[2], lp[2]);
            split2h(v[6], v[7], hp[3], lp[3]);
            *(uint4*)(As_hi[buf^1] + sbase) = make_uint4(hp[0], hp[1], hp[2], hp[3]);
            *(uint4*)(As_lo[buf^1] + sbase) = make_uint4(lp[0], lp[1], lp[2], lp[3]);
        }
        __syncthreads();
    }

    // ---- epilogue: bias + ReLU -> h A-fragments (fp16 hi/lo) ----
    #pragma unroll
    for (int mt = 0; mt < 2; mt++) {
        int mblock = blockIdx.x*4 + warp_m*2 + mt;
        #pragma unroll
        for (int fp = 0; fp < 4; fp++) {
            int f0 = 2*fp, f1 = 2*fp + 1;
            int kbh = warp_n*4 + fp;
            int col0 = (warp_n*8 + f0)*8 + (lane & 3)*2;
            float2 bb0 = *(const float2*)(b1 + col0);
            float2 bb1 = *(const float2*)(b1 + col0 + 8);
            float v0 = fmaxf(acc[mt][f0][0] + bb0.x, 0.0f);
            float v1 = fmaxf(acc[mt][f0][1] + bb0.y, 0.0f);
            float v2 = fmaxf(acc[mt][f0][2] + bb0.x, 0.0f);
            float v3 = fmaxf(acc[mt][f0][3] + bb0.y, 0.0f);
            float v4 = fmaxf(acc[mt][f1][0] + bb1.x, 0.0f);
            float v5 = fmaxf(acc[mt][f1][1] + bb1.y, 0.0f);
            float v6 = fmaxf(acc[mt][f1][2] + bb1.x, 0.0f);
            float v7 = fmaxf(acc[mt][f1][3] + bb1.y, 0.0f);
            uint32_t a0h, a0l, a1h, a1l, a2h, a2l, a3h, a3l;
            split2h(v0, v1, a0h, a0l);
            split2h(v2, v3, a1h, a1l);
            split2h(v4, v5, a2h, a2l);
            split2h(v6, v7, a3h, a3l);
            int fidx = (mblock*NKB2 + kbh)*32 + lane;
            ((uint4*)g_hfrag_hi)[fidx] = make_uint4(a0h, a1h, a2h, a3h);
            ((uint4*)g_hfrag_lo)[fidx] = make_uint4(a0l, a1l, a2l, a3l);
        }
    }
}

// ---------------- GEMM2: Linear2 + ReLU, fragment path, 2-MMA fp16 ----------------
__global__ __launch_bounds__(256, 2)
void gemm2_kernel(const float* __restrict__ b2, float* __restrict__ out) {
    int tid = threadIdx.x;
    int wid = tid >> 5;
    int lane = tid & 31;
    int g = blockIdx.x * 8 + wid;
    int mstrip = g >> 2;
    int nq = g & 3;

    const uint4* HF = (const uint4*)g_hfrag_hi;
    const uint4* LF = (const uint4*)g_hfrag_lo;
    int mb0 = mstrip * 2;

    float acc[2][8][4];
    #pragma unroll
    for (int i = 0; i < 2; i++)
        #pragma unroll
        for (int j = 0; j < 8; j++)
            #pragma unroll
            for (int q = 0; q < 4; q++) acc[i][j][q] = 0.0f;

    uint4 th[2], tl[2];
    #pragma unroll
    for (int mt = 0; mt < 2; mt++) {
        th[mt] = HF[((mb0 + mt)*NKB2 + 0)*32 + lane];
        tl[mt] = LF[((mb0 + mt)*NKB2 + 0)*32 + lane];
    }

    for (int kb = 0; kb < NKB2; kb++) {
        uint32_t ah[2][4], al[2][4];
        #pragma unroll
        for (int mt = 0; mt < 2; mt++) {
            ah[mt][0] = th[mt].x; ah[mt][1] = th[mt].y; ah[mt][2] = th[mt].z; ah[mt][3] = th[mt].w;
            al[mt][0] = tl[mt].x; al[mt][1] = tl[mt].y; al[mt][2] = tl[mt].z; al[mt][3] = tl[mt].w;
        }
        if (kb + 1 < NKB2) {
            #pragma unroll
            for (int mt = 0; mt < 2; mt++) {
                th[mt] = HF[((mb0 + mt)*NKB2 + kb + 1)*32 + lane];
                tl[mt] = LF[((mb0 + mt)*NKB2 + kb + 1)*32 + lane];
            }
        }
        #pragma unroll
        for (int nb = 0; nb < 8; nb++) {
            int nblock = nq*8 + nb;
            uint2 bb = *(const uint2*)&g_w2f[(nblock*NKB2 + kb)*64 + lane*2];
            #pragma unroll
            for (int mt = 0; mt < 2; mt++) {
                float* d = acc[mt][nb];
                MMA_F16(d, ah[mt], bb.x, bb.y);
                MMA_F16(d, al[mt], bb.x, bb.y);
            }
        }
    }

    #pragma unroll
    for (int mt = 0; mt < 2; mt++) {
        int r0 = mstrip*32 + mt*16 + (lane >> 2);
        #pragma unroll
        for (int nb = 0; nb < 8; nb++) {
            int col = (nq*8 + nb)*8 + (lane & 3)*2;
            float2 bb = *(const float2*)(b2 + col);
            float2 o0, o1;
            o0.x = fmaxf(acc[mt][nb][0] + bb.x, 0.0f);
            o0.y = fmaxf(acc[mt][nb][1] + bb.y, 0.0f);
            o1.x = fmaxf(acc[mt][nb][2] + bb.x, 0.0f);
            o1.y = fmaxf(acc[mt][nb][3] + bb.y, 0.0f);
            *(float2*)(out + (size_t)r0 * OUTD + col) = o0;
            *(float2*)(out + (size_t)(r0+8) * OUTD + col) = o1;
        }
    }
}

// ---------------- launch ----------------
extern "C" void kernel_launch(void* const* d_in, const int* in_sizes, int n_in,
                              void* d_out, int out_size) {
    const float* x          = (const float*)d_in[0];
    const float* pos        = (const float*)d_in[1];
    const float* x_skip     = (const float*)d_in[3];
    const float* pos_skip   = (const float*)d_in[4];
    const int*   batch_skip = (const int*)d_in[5];
    const float* W1         = (const float*)d_in[6];
    const float* b1         = (const float*)d_in[7];
    const float* W2         = (const float*)d_in[8];
    const float* b2         = (const float*)d_in[9];
    float* out = (float*)d_out;

    misc_kernel<<<512 + 80 + 768, 256>>>(pos, pos_skip, batch_skip, W1, W2, out);
    knn_merge_kernel<<<MTOT/256, 256>>>(pos, pos_skip);
    gemm1_kernel<<<MTOT/64, 256>>>(x, x_skip, b1);
    gemm2_kernel<<<1024, 256>>>(b2, out);
}

// round 16
// speedup vs baseline: 1.2485x; 1.1497x over previous
#include <cuda_runtime.h>
#include <cuda_fp16.h>
#include <cstdint>

// ---------------- problem constants ----------------
#define NB   8
#define NC   2048
#define NF   8192
#define CDIM 256
#define CS   64
#define OUTD 256
#define MTOT (NB*NF)        // 65536
#define K1   (CDIM+CS)      // 320
#define HSIZE (MTOT*OUTD)
#define NKB1 20             // K1/16 k-blocks for GEMM1
#define NKB2 16             // 256/16 k-blocks for GEMM2
#define NNB  32             // 256/8 n-blocks
#define HALF 1024           // candidates per KNN phase-A block

// ---------------- scratch (static device globals) ----------------
__device__ int   g_idx[MTOT*3];
__device__ float g_w[MTOT*3];
__device__ float g_ps[2*MTOT*3];
__device__ int   g_pi[2*MTOT*3];
// weights as single-fp16 mma B-fragments: [nblock][kblock][lane][2] u32
__device__ __align__(16) uint32_t g_w1f[NNB*NKB1*64];
__device__ __align__(16) uint32_t g_w2f[NNB*NKB2*64];

// ---------------- helpers ----------------
__device__ __forceinline__ uint32_t smem_u32(const void* p) {
    uint32_t a;
    asm("{ .reg .u64 t; cvta.to.shared.u64 t, %1; cvt.u32.u64 %0, t; }" : "=r"(a) : "l"(p));
    return a;
}

#define LDSM_X4(r0, r1, r2, r3, addr) \
    asm volatile("ldmatrix.sync.aligned.m8n8.x4.shared.b16 {%0,%1,%2,%3}, [%4];" \
        : "=r"(r0), "=r"(r1), "=r"(r2), "=r"(r3) : "r"(addr))

#define MMA_F16(d, a, b0, b1) \
    asm volatile("mma.sync.aligned.m16n8k16.row.col.f32.f16.f16.f32 " \
        "{%0,%1,%2,%3}, {%4,%5,%6,%7}, {%8,%9}, {%0,%1,%2,%3};" \
        : "+f"((d)[0]), "+f"((d)[1]), "+f"((d)[2]), "+f"((d)[3]) \
        : "r"((a)[0]), "r"((a)[1]), "r"((a)[2]), "r"((a)[3]), "r"(b0), "r"(b1))

__device__ __forceinline__ uint32_t packh(__half a, __half b) {
    return ((uint32_t)__half_as_ushort(b) << 16) | (uint32_t)__half_as_ushort(a);
}

__device__ __forceinline__ void split2h(float v0, float v1, uint32_t& hi, uint32_t& lo) {
    __half h0 = __float2half_rn(v0);
    __half h1 = __float2half_rn(v1);
    __half l0 = __float2half_rn(v0 - __half2float(h0));
    __half l1 = __float2half_rn(v1 - __half2float(h1));
    hi = packh(h0, h1);
    lo = packh(l0, l1);
}

__device__ __forceinline__ void ins3(float s, int j,
                                     float& s0, float& s1, float& s2,
                                     int& i0, int& i1, int& i2) {
    if (s > s2) {
        if (s > s1) {
            s2 = s1; i2 = i1;
            if (s > s0) { s1 = s0; i1 = i0; s0 = s; i0 = j; }
            else        { s1 = s;  i1 = j; }
        } else { s2 = s; i2 = j; }
    }
}

// ---------------- fused misc: knnA (0..511), prep (512..591), aux (592..1359) ----------------
__global__ void misc_kernel(const float* __restrict__ pos,
                            const float* __restrict__ pos_skip,
                            const int*  __restrict__ batch_skip,
                            const float* __restrict__ W1,
                            const float* __restrict__ W2,
                            float* __restrict__ out) {
    __shared__ float sx[HALF], sy[HALF], sz[HALF], sw[HALF];
    int blk = blockIdx.x;
    int tid = threadIdx.x;

    if (blk < 512) {
        int half = blk & 1;
        int grp = blk >> 1;
        int b = grp >> 5;
        int blk_in = grp & 31;
        int jbase = half * HALF;
        const float* cp = pos + ((size_t)b * NC + jbase) * 3;
        for (int i = tid; i < HALF; i += 256) {
            float cx = cp[i*3+0], cy = cp[i*3+1], cz = cp[i*3+2];
            sx[i] = cx; sy[i] = cy; sz[i] = cz;
            sw[i] = -0.5f * (cx*cx + cy*cy + cz*cz);
        }
        __syncthreads();

        int p = b * NF + blk_in * 256 + tid;
        float fx = pos_skip[p*3+0], fy = pos_skip[p*3+1], fz = pos_skip[p*3+2];

        float a0 = -1e30f, a1 = -1e30f, a2 = -1e30f;
        int   ai0 = 0,     ai1 = 0,     ai2 = 0;

        #pragma unroll 2
        for (int j = 0; j < HALF; j += 4) {
            float4 X = *(const float4*)&sx[j];
            float4 Y = *(const float4*)&sy[j];
            float4 Z = *(const float4*)&sz[j];
            float4 W = *(const float4*)&sw[j];
            float sa = fmaf(fz, Z.x, fmaf(fy, Y.x, fmaf(fx, X.x, W.x)));
            float sb = fmaf(fz, Z.y, fmaf(fy, Y.y, fmaf(fx, X.y, W.y)));
            float sc = fmaf(fz, Z.z, fmaf(fy, Y.z, fmaf(fx, X.z, W.z)));
            float sd = fmaf(fz, Z.w, fmaf(fy, Y.w, fmaf(fx, X.w, W.w)));
            float smax = fmaxf(fmaxf(sa, sb), fmaxf(sc, sd));
            if (smax > a2) {
                ins3(sa, j+0, a0, a1, a2, ai0, ai1, ai2);
                ins3(sb, j+1, a0, a1, a2, ai0, ai1, ai2);
                ins3(sc, j+2, a0, a1, a2, ai0, ai1, ai2);
                ins3(sd, j+3, a0, a1, a2, ai0, ai1, ai2);
            }
        }

        int base = (half * MTOT + p) * 3;
        g_ps[base+0] = a0; g_ps[base+1] = a1; g_ps[base+2] = a2;
        g_pi[base+0] = b*NC + jbase + ai0;
        g_pi[base+1] = b*NC + jbase + ai1;
        g_pi[base+2] = b*NC + jbase + ai2;
    } else if (blk < 512 + 80) {
        // ---- weight prep: W^T -> single-fp16 B-fragments ----
        int t = (blk - 512) * 256 + tid;
        if (t < NNB * NKB1 * 32) {
            int lane = t & 31;
            int kb = (t >> 5) % NKB1;
            int nb = t / (32 * NKB1);
            int n = nb*8 + (lane >> 2);
            int k0 = kb*16 + (lane & 3)*2;
            float v0 = W1[(k0+0)*OUTD + n], v1 = W1[(k0+1)*OUTD + n];
            float v8 = W1[(k0+8)*OUTD + n], v9 = W1[(k0+9)*OUTD + n];
            int idx = (nb*NKB1 + kb)*64 + lane*2;
            g_w1f[idx]   = packh(__float2half_rn(v0), __float2half_rn(v1));
            g_w1f[idx+1] = packh(__float2half_rn(v8), __float2half_rn(v9));
        }
        if (t < NNB * NKB2 * 32) {
            int lane = t & 31;
            int kb = (t >> 5) & 15;
            int nb = t >> 9;
            int n = nb*8 + (lane >> 2);
            int k0 = kb*16 + (lane & 3)*2;
            float v0 = W2[(k0+0)*OUTD + n], v1 = W2[(k0+1)*OUTD + n];
            float v8 = W2[(k0+8)*OUTD + n], v9 = W2[(k0+9)*OUTD + n];
            int idx = (nb*NKB2 + kb)*64 + lane*2;
            g_w2f[idx]   = packh(__float2half_rn(v0), __float2half_rn(v1));
            g_w2f[idx+1] = packh(__float2half_rn(v8), __float2half_rn(v9));
        }
    } else {
        int i = (blk - 592) * 256 + tid;
        if (i < MTOT*3) out[HSIZE + i] = pos_skip[i];
        if (i < MTOT)   out[HSIZE + MTOT*3 + i] = (float)batch_skip[i];
    }
}

// ---------------- KNN phase B: merge halves, exact distances, weights ----------------
__global__ void knn_merge_kernel(const float* __restrict__ pos,
                                 const float* __restrict__ pos_skip) {
    int p = blockIdx.x * 256 + threadIdx.x;
    int b0 = p * 3;
    int b1 = (MTOT + p) * 3;

    float s0 = g_ps[b0+0], s1 = g_ps[b0+1], s2 = g_ps[b0+2];
    int   i0 = g_pi[b0+0], i1 = g_pi[b0+1], i2 = g_pi[b0+2];
    ins3(g_ps[b1+0], g_pi[b1+0], s0, s1, s2, i0, i1, i2);
    ins3(g_ps[b1+1], g_pi[b1+1], s0, s1, s2, i0, i1, i2);
    ins3(g_ps[b1+2], g_pi[b1+2], s0, s1, s2, i0, i1, i2);

    float fx = pos_skip[p*3+0], fy = pos_skip[p*3+1], fz = pos_skip[p*3+2];
    float dx, dy, dz;
    dx = fx - pos[i0*3+0]; dy = fy - pos[i0*3+1]; dz = fz - pos[i0*3+2];
    float d0 = dx*dx + dy*dy + dz*dz;
    dx = fx - pos[i1*3+0]; dy = fy - pos[i1*3+1]; dz = fz - pos[i1*3+2];
    float d1 = dx*dx + dy*dy + dz*dz;
    dx = fx - pos[i2*3+0]; dy = fy - pos[i2*3+1]; dz = fz - pos[i2*3+2];
    float d2 = dx*dx + dy*dy + dz*dz;
    float w0 = 1.0f / fmaxf(d0, 1e-16f);
    float w1 = 1.0f / fmaxf(d1, 1e-16f);
    float w2 = 1.0f / fmaxf(d2, 1e-16f);
    float inv = 1.0f / (w0 + w1 + w2);
    g_idx[p*3+0] = i0;
    g_idx[p*3+1] = i1;
    g_idx[p*3+2] = i2;
    g_w[p*3+0] = w0 * inv;
    g_w[p*3+1] = w1 * inv;
    g_w[p*3+2] = w2 * inv;
}

// ---------------- fused GEMM: gather+interp + Linear1 + ReLU + Linear2 + ReLU ----------------
// CTA: 64 rows x 256 cols, 8 warps (warp_m strips of 32, warp_n quarters of 64).
// h exchanged through dynamic SMEM (fp16 hi/lo planes, RSH-padded), overlaying the
// double-buffered A tiles (dead after phase 1).
#define RS  40    // phase-1 A-tile row stride (fp16)
#define RSH 264   // h plane row stride (fp16)
// dynamic smem layout:
//   [0 .. 20480)        : phase-1 A tiles  (AsHi0, AsLo0, AsHi1, AsLo1; 5120 B each)
//   [0 .. 33792)        : h hi plane (overlays A tiles in phase 2)
//   [33792 .. 67584)    : h lo plane
#define SM_AHI(b) ((b) * 10240)
#define SM_ALO(b) ((b) * 10240 + 5120)
#define SM_HHI    0
#define SM_HLO    33792
#define SMEM_DYN  67584

__global__ __launch_bounds__(256, 2)
void fused_gemm_kernel(const float* __restrict__ x,
                       const float* __restrict__ x_skip,
                       const float* __restrict__ b1,
                       const float* __restrict__ b2,
                       float* __restrict__ out) {
    extern __shared__ char sm[];
    __half* smh = (__half*)sm;

    int tid = threadIdx.x;
    int wid = tid >> 5;
    int lane = tid & 31;
    int warp_m = wid & 1;
    int warp_n = wid >> 1;
    int bm = blockIdx.x * 64;

    int lrow = tid >> 2;
    int koff = (tid & 3) * 8;
    int r = bm + lrow;
    int i0 = g_idx[r*3+0] * CDIM, i1 = g_idx[r*3+1] * CDIM, i2 = g_idx[r*3+2] * CDIM;
    float w0 = g_w[r*3+0], w1 = g_w[r*3+1], w2 = g_w[r*3+2];
    int sbase = lrow * RS + koff;   // fp16 units within an A plane

    uint32_t smbase = smem_u32(sm);
    uint32_t aOff = (uint32_t)(((warp_m*32 + (lane & 15)) * RS + (lane >> 4) * 8) * 2);
    uint32_t sH[2] = { smbase + SM_AHI(0) + aOff, smbase + SM_AHI(1) + aOff };
    uint32_t sL[2] = { smbase + SM_ALO(0) + aOff, smbase + SM_ALO(1) + aOff };

    float acc[2][8][4];
    #pragma unroll
    for (int i = 0; i < 2; i++)
        #pragma unroll
        for (int j = 0; j < 8; j++)
            #pragma unroll
            for (int q = 0; q < 4; q++) acc[i][j][q] = 0.0f;

    // ---- phase 1 prologue: build chunk 0 into buf 0 ----
    {
        float4 a0 = *(const float4*)(x + i0 + koff);
        float4 a1 = *(const float4*)(x + i0 + koff + 4);
        float4 b0 = *(const float4*)(x + i1 + koff);
        float4 b1v = *(const float4*)(x + i1 + koff + 4);
        float4 c0 = *(const float4*)(x + i2 + koff);
        float4 c1 = *(const float4*)(x + i2 + koff + 4);
        uint32_t hp[4], lp[4];
        split2h(w0*a0.x + w1*b0.x + w2*c0.x,  w0*a0.y + w1*b0.y + w2*c0.y,  hp[0], lp[0]);
        split2h(w0*a0.z + w1*b0.z + w2*c0.z,  w0*a0.w + w1*b0.w + w2*c0.w,  hp[1], lp[1]);
        split2h(w0*a1.x + w1*b1v.x + w2*c1.x, w0*a1.y + w1*b1v.y + w2*c1.y, hp[2], lp[2]);
        split2h(w0*a1.z + w1*b1v.z + w2*c1.z, w0*a1.w + w1*b1v.w + w2*c1.w, hp[3], lp[3]);
        *(uint4*)(smh + SM_AHI(0)/2 + sbase) = make_uint4(hp[0], hp[1], hp[2], hp[3]);
        *(uint4*)(smh + SM_ALO(0)/2 + sbase) = make_uint4(lp[0], lp[1], lp[2], lp[3]);
    }
    __syncthreads();

    for (int c = 0; c < 10; c++) {
        int buf = c & 1;
        float4 ga0, ga1, gb0, gb1, gc0, gc1;
        bool have_next = (c + 1 < 10);
        bool next_is_x = ((c + 1) * 32 < CDIM);
        if (have_next) {
            if (next_is_x) {
                int k = (c + 1) * 32 + koff;
                ga0 = *(const float4*)(x + i0 + k);
                ga1 = *(const float4*)(x + i0 + k + 4);
                gb0 = *(const float4*)(x + i1 + k);
                gb1 = *(const float4*)(x + i1 + k + 4);
                gc0 = *(const float4*)(x + i2 + k);
                gc1 = *(const float4*)(x + i2 + k + 4);
            } else {
                int ks = (c + 1) * 32 - CDIM + koff;
                ga0 = *(const float4*)(x_skip + (size_t)r * CS + ks);
                ga1 = *(const float4*)(x_skip + (size_t)r * CS + ks + 4);
            }
        }

        #pragma unroll
        for (int ks = 0; ks < 2; ks++) {
            int kb = c*2 + ks;
            uint32_t ko = ks * 32;
            uint32_t ah[2][4], al[2][4];
            #pragma unroll
            for (int mt = 0; mt < 2; mt++) {
                LDSM_X4(ah[mt][0], ah[mt][1], ah[mt][2], ah[mt][3], sH[buf] + mt*16*RS*2 + ko);
                LDSM_X4(al[mt][0], al[mt][1], al[mt][2], al[mt][3], sL[buf] + mt*16*RS*2 + ko);
            }
            uint2 bb = *(const uint2*)&g_w1f[((warp_n*8)*NKB1 + kb)*64 + lane*2];
            #pragma unroll
            for (int nb = 0; nb < 8; nb++) {
                uint2 bbn;
                if (nb < 7) {
                    int nblock = warp_n*8 + nb + 1;
                    bbn = *(const uint2*)&g_w1f[(nblock*NKB1 + kb)*64 + lane*2];
                }
                #pragma unroll
                for (int mt = 0; mt < 2; mt++) {
                    float* d = acc[mt][nb];
                    MMA_F16(d, ah[mt], bb.x, bb.y);
                    MMA_F16(d, al[mt], bb.x, bb.y);
                }
                bb = bbn;
            }
        }

        if (have_next) {
            float v[8];
            if (next_is_x) {
                v[0] = w0*ga0.x + w1*gb0.x + w2*gc0.x;
                v[1] = w0*ga0.y + w1*gb0.y + w2*gc0.y;
                v[2] = w0*ga0.z + w1*gb0.z + w2*gc0.z;
                v[3] = w0*ga0.w + w1*gb0.w + w2*gc0.w;
                v[4] = w0*ga1.x + w1*gb1.x + w2*gc1.x;
                v[5] = w0*ga1.y + w1*gb1.y + w2*gc1.y;
                v[6] = w0*ga1.z + w1*gb1.z + w2*gc1.z;
                v[7] = w0*ga1.w + w1*gb1.w + w2*gc1.w;
            } else {
                v[0] = ga0.x; v[1] = ga0.y; v[2] = ga0.z; v[3] = ga0.w;
                v[4] = ga1.x; v[5] = ga1.y; v[6] = ga1.z; v[7] = ga1.w;
            }
            uint32_t hp[4], lp[4];
            split2h(v[0], v[1], hp[0], lp[0]);
            split2h(v[2], v[3], hp[1], lp[1]);
            split2h(v[4], v[5], hp[2], lp[2]);
            split2h(v[6], v[7], hp[3], lp[3]);
            *(uint4*)(smh + SM_AHI(buf^1)/2 + sbase) = make_uint4(hp[0], hp[1], hp[2], hp[3]);
            *(uint4*)(smh + SM_ALO(buf^1)/2 + sbase) = make_uint4(lp[0], lp[1], lp[2], lp[3]);
        }
        __syncthreads();
    }

    // ---- phase boundary: bias + ReLU, split to fp16 hi/lo, write h planes ----
    __half* hHi = smh + SM_HHI/2;
    __half* hLo = smh + SM_HLO/2;
    #pragma unroll
    for (int mt = 0; mt < 2; mt++) {
        int lr0 = warp_m*32 + mt*16 + (lane >> 2);
        #pragma unroll
        for (int f = 0; f < 8; f++) {
            int col = warp_n*64 + f*8 + (lane & 3)*2;
            float2 bb = *(const float2*)(b1 + col);
            float v0 = fmaxf(acc[mt][f][0] + bb.x, 0.0f);
            float v1 = fmaxf(acc[mt][f][1] + bb.y, 0.0f);
            float v2 = fmaxf(acc[mt][f][2] + bb.x, 0.0f);
            float v3 = fmaxf(acc[mt][f][3] + bb.y, 0.0f);
            uint32_t h01, l01, h23, l23;
            split2h(v0, v1, h01, l01);
            split2h(v2, v3, h23, l23);
            *(uint32_t*)(hHi + lr0*RSH + col)     = h01;
            *(uint32_t*)(hLo + lr0*RSH + col)     = l01;
            *(uint32_t*)(hHi + (lr0+8)*RSH + col) = h23;
            *(uint32_t*)(hLo + (lr0+8)*RSH + col) = l23;
        }
    }
    __syncthreads();

    // ---- phase 2: out = relu(h @ W2 + b2) ----
    float acc2[2][8][4];
    #pragma unroll
    for (int i = 0; i < 2; i++)
        #pragma unroll
        for (int j = 0; j < 8; j++)
            #pragma unroll
            for (int q = 0; q < 4; q++) acc2[i][j][q] = 0.0f;

    uint32_t hOff = (uint32_t)(((warp_m*32 + (lane & 15)) * RSH + (lane >> 4) * 8) * 2);
    uint32_t sHH = smbase + SM_HHI + hOff;
    uint32_t sHL = smbase + SM_HLO + hOff;

    for (int kb = 0; kb < NKB2; kb++) {
        uint32_t ko = kb * 32;
        uint32_t ah[2][4], al[2][4];
        #pragma unroll
        for (int mt = 0; mt < 2; mt++) {
            LDSM_X4(ah[mt][0], ah[mt][1], ah[mt][2], ah[mt][3], sHH + mt*16*RSH*2 + ko);
            LDSM_X4(al[mt][0], al[mt][1], al[mt][2], al[mt][3], sHL + mt*16*RSH*2 + ko);
        }
        uint2 bb = *(const uint2*)&g_w2f[((warp_n*8)*NKB2 + kb)*64 + lane*2];
        #pragma unroll
        for (int nb = 0; nb < 8; nb++) {
            uint2 bbn;
            if (nb < 7) {
                int nblock = warp_n*8 + nb + 1;
                bbn = *(const uint2*)&g_w2f[(nblock*NKB2 + kb)*64 + lane*2];
            }
            #pragma unroll
            for (int mt = 0; mt < 2; mt++) {
                float* d = acc2[mt][nb];
                MMA_F16(d, ah[mt], bb.x, bb.y);
                MMA_F16(d, al[mt], bb.x, bb.y);
            }
            bb = bbn;
        }
    }

    // ---- epilogue: bias + ReLU -> fp32 out ----
    #pragma unroll
    for (int mt = 0; mt < 2; mt++) {
        int r0 = bm + warp_m*32 + mt*16 + (lane >> 2);
        #pragma unroll
        for (int nb = 0; nb < 8; nb++) {
            int col = warp_n*64 + nb*8 + (lane & 3)*2;
            float2 bb = *(const float2*)(b2 + col);
            float2 o0, o1;
            o0.x = fmaxf(acc2[mt][nb][0] + bb.x, 0.0f);
            o0.y = fmaxf(acc2[mt][nb][1] + bb.y, 0.0f);
            o1.x = fmaxf(acc2[mt][nb][2] + bb.x, 0.0f);
            o1.y = fmaxf(acc2[mt][nb][3] + bb.y, 0.0f);
            *(float2*)(out + (size_t)r0 * OUTD + col) = o0;
            *(float2*)(out + (size_t)(r0+8) * OUTD + col) = o1;
        }
    }
}

// ---------------- launch ----------------
extern "C" void kernel_launch(void* const* d_in, const int* in_sizes, int n_in,
                              void* d_out, int out_size) {
    const float* x          = (const float*)d_in[0];
    const float* pos        = (const float*)d_in[1];
    const float* x_skip     = (const float*)d_in[3];
    const float* pos_skip   = (const float*)d_in[4];
    const int*   batch_skip = (const int*)d_in[5];
    const float* W1         = (const float*)d_in[6];
    const float* b1         = (const float*)d_in[7];
    const float* W2         = (const float*)d_in[8];
    const float* b2         = (const float*)d_in[9];
    float* out = (float*)d_out;

    // idempotent; host-side, not a graph node (replay never re-executes this)
    cudaFuncSetAttribute(fused_gemm_kernel,
                         cudaFuncAttributeMaxDynamicSharedMemorySize, SMEM_DYN);

    misc_kernel<<<512 + 80 + 768, 256>>>(pos, pos_skip, batch_skip, W1, W2, out);
    knn_merge_kernel<<<MTOT/256, 256>>>(pos, pos_skip);
    fused_gemm_kernel<<<MTOT/64, 256, SMEM_DYN>>>(x, x_skip, b1, b2, out);
}